// round 14
// baseline (speedup 1.0000x reference)
#include <cuda_runtime.h>
#include <cuda_bf16.h>
#include <cstdint>

// Problem constants
#define B_  32
#define Q_  500
#define T_  128
#define NC_ 80
#define BQ_ (B_ * Q_)     // 16000
#define BT_ (B_ * T_)     // 4096

#define TR 64             // tile rows (two 32-row halves per block)
#define TC 128            // tile cols
#define SIDX(c) ((c) + ((c) >> 3))   // conflict-free float4 swizzle

// ---------------------------------------------------------------------------
// FFMA-imm helpers: rt_SMSP=1. Immediates perturbed 1 ulp so ptxas can't fold.
// ---------------------------------------------------------------------------
__device__ __forceinline__ float fadd1(float a, float c) {   // ~ a + c
    float d; asm("fma.rn.f32 %0, %1, 0f3F800001, %2;" : "=f"(d) : "f"(a), "f"(c)); return d;
}
__device__ __forceinline__ float fsub1(float a, float b) {   // ~ a - b
    float d; asm("fma.rn.f32 %0, %1, 0fBF800001, %2;" : "=f"(d) : "f"(b), "f"(a)); return d;
}
__device__ __forceinline__ float fnma2(float x, float c) {   // ~ c - 2*x
    float d; asm("fma.rn.f32 %0, %1, 0fC0000001, %2;" : "=f"(d) : "f"(x), "f"(c)); return d;
}

// ---------------------------------------------------------------------------
// Packed f32x2 helpers — ONLY add/sub (min/max.f32x2 do not exist in PTX).
// ---------------------------------------------------------------------------
__device__ __forceinline__ uint64_t pk2(float x, float y) {
    uint64_t r; asm("mov.b64 %0, {%1, %2};" : "=l"(r) : "f"(x), "f"(y)); return r;
}
__device__ __forceinline__ void upk2(uint64_t v, float& x, float& y) {
    asm("mov.b64 {%0, %1}, %2;" : "=f"(x), "=f"(y) : "l"(v));
}
__device__ __forceinline__ uint64_t f2add(uint64_t a, uint64_t b) {
    uint64_t d; asm("add.rn.f32x2 %0, %1, %2;" : "=l"(d) : "l"(a), "l"(b)); return d;
}
__device__ __forceinline__ uint64_t f2sub(uint64_t a, uint64_t b) {
    uint64_t d; asm("sub.rn.f32x2 %0, %1, %2;" : "=l"(d) : "l"(a), "l"(b)); return d;
}

// Scratch (device globals: allocation-free rule). SoA float4 layout.
__device__ float  g_prob[BQ_ * NC_];   // pv = 2 - 2*softmax, [row][cls]
__device__ float4 g_rowA[BQ_];         // 5*nx1, 5*ny1, 5*nx2, 5*ny2
__device__ float4 g_rowB[BQ_];         // x1, y1, x2, y2
__device__ float4 g_rowC[BQ_];         // w, h, area, 0
__device__ float4 g_colA[BT_];
__device__ float4 g_colB[BT_];
__device__ float4 g_colC[BT_];         // w, h, area, cls (int bits)

// ---------------------------------------------------------------------------
// Fused prep: blocks [0, BQ_/8) do softmax rows; blocks after do targets.
// ---------------------------------------------------------------------------
#define ROWBLKS (BQ_ / 8)   // 2000

__global__ void prep_kernel(const float* __restrict__ logits,
                            const float* __restrict__ boxes,
                            const float* __restrict__ img_sz,
                            const float* __restrict__ tboxes,
                            const int*   __restrict__ tlabels,
                            const float* __restrict__ img_sz_tgt)
{
    if (blockIdx.x < ROWBLKS) {
        // ---- per-query: softmax (stored as pv = 2-2p) + box precompute ----
        int row  = blockIdx.x * 8 + (threadIdx.x >> 5);
        int lane = threadIdx.x & 31;

        const float* lg = logits + (size_t)row * NC_;
        float v0 = lg[lane];
        float v1 = lg[lane + 32];
        float v2 = (lane < 16) ? lg[lane + 64] : -3.4e38f;

        float m = fmaxf(v0, fmaxf(v1, v2));
        #pragma unroll
        for (int o = 16; o; o >>= 1) m = fmaxf(m, __shfl_xor_sync(0xffffffffu, m, o));

        float e0 = __expf(v0 - m);
        float e1 = __expf(v1 - m);
        float e2 = (lane < 16) ? __expf(v2 - m) : 0.f;
        float s = e0 + e1 + e2;
        #pragma unroll
        for (int o = 16; o; o >>= 1) s += __shfl_xor_sync(0xffffffffu, s, o);

        float ninv2 = __fdividef(-2.f, s);
        float* pr = g_prob + (size_t)row * NC_;
        pr[lane]      = fmaf(e0, ninv2, 2.f);
        pr[lane + 32] = fmaf(e1, ninv2, 2.f);
        if (lane < 16) pr[lane + 64] = fmaf(e2, ninv2, 2.f);

        if (lane == 0) {
            int b = row / Q_;
            const float* bx = boxes + (size_t)row * 4;
            float x1 = bx[0], y1 = bx[1], x2 = bx[2], y2 = bx[3];
            float s0 = img_sz[b * 4 + 0], s1 = img_sz[b * 4 + 1];
            float s2 = img_sz[b * 4 + 2], s3 = img_sz[b * 4 + 3];
            float w = x2 - x1, h = y2 - y1;
            g_rowA[row] = make_float4(__fdividef(5.f * x1, s0),
                                      __fdividef(5.f * y1, s1),
                                      __fdividef(5.f * x2, s2),
                                      __fdividef(5.f * y2, s3));
            g_rowB[row] = make_float4(x1, y1, x2, y2);
            g_rowC[row] = make_float4(w, h, w * h, 0.f);
        }
    } else {
        // ---- per-target: box precompute + class id ----
        int j = (blockIdx.x - ROWBLKS) * blockDim.x + threadIdx.x;
        if (j >= BT_) return;

        const float* bx = tboxes + (size_t)j * 4;
        const float* sz = img_sz_tgt + (size_t)j * 4;
        float x1 = bx[0], y1 = bx[1], x2 = bx[2], y2 = bx[3];
        float w = x2 - x1, h = y2 - y1;
        g_colA[j] = make_float4(__fdividef(5.f * x1, sz[0]),
                                __fdividef(5.f * y1, sz[1]),
                                __fdividef(5.f * x2, sz[2]),
                                __fdividef(5.f * y2, sz[3]));
        g_colB[j] = make_float4(x1, y1, x2, y2);
        g_colC[j] = make_float4(w, h, w * h, __int_as_float(tlabels[j]));
    }
}

// ---------------------------------------------------------------------------
// Main: cost matrix [BQ, BT]. Round-9 structure/math, but each block covers
// a 64x128 tile: two 32-row halves share one col smem fill + one barrier,
// halving per-block overhead (8000 blocks instead of 16000).
// ---------------------------------------------------------------------------
__global__ __launch_bounds__(256, 3)
void cost_kernel(float* __restrict__ out)
{
    __shared__ float4 srA[TR], srB[TR], srC[TR];       // broadcast reads
    __shared__ float4 scA[TC + TC/8], scB[TC + TC/8], scC[TC + TC/8];

    const int r0 = blockIdx.y * TR;
    const int c0 = blockIdx.x * TC;
    const int tid = threadIdx.x;

    if (tid < TC) {
        int si = SIDX(tid);
        scA[si] = g_colA[c0 + tid];
        scB[si] = g_colB[c0 + tid];
        scC[si] = g_colC[c0 + tid];
    } else if (tid < TC + TR) {
        int r = tid - TC;
        srA[r] = g_rowA[r0 + r];
        srB[r] = g_rowB[r0 + r];
        srC[r] = g_rowC[r0 + r];
    }
    __syncthreads();

    const int tc = tid & 31;       // column group (4 consecutive cols)
    const int tr = tid >> 5;       // warp -> row group
    const int cloc = tc * 4;

    #pragma unroll
    for (int h = 0; h < 2; h++) {
        const int rloc = tr * 4 + h * 32;

        // Row data into registers (broadcast LDS, N=1)
        float Rx1[4], Ry1[4], Rx2[4], Ry2[4];
        float Ra[4];
        uint64_t Rn1[4], Rn2[4], Rwh[4];
        #pragma unroll
        for (int rr = 0; rr < 4; rr++) {
            float4 A  = srA[rloc + rr];
            float4 Bv = srB[rloc + rr];
            float4 Cv = srC[rloc + rr];
            Rn1[rr]  = pk2(A.x, A.y);
            Rn2[rr]  = pk2(A.z, A.w);
            Rx1[rr]  = Bv.x; Ry1[rr]  = Bv.y; Rx2[rr]  = Bv.z; Ry2[rr]  = Bv.w;
            Rwh[rr]  = pk2(Cv.x, Cv.y);
            Ra[rr]   = Cv.z;
        }

        const float* prow = g_prob + (size_t)(r0 + rloc) * NC_;

        float res[4][4];

        #pragma unroll
        for (int cc = 0; cc < 4; cc++) {
            const int si = SIDX(cloc + cc);
            const float4 A  = scA[si];   // 5*norm coords
            const float4 Bv = scB[si];   // xyxy
            const float4 Cv = scC[si];   // w,h,area,clsbits
            const uint64_t cn1 = pk2(A.x, A.y);
            const uint64_t cn2 = pk2(A.z, A.w);
            const uint64_t cwh = pk2(Cv.x, Cv.y);
            const float ctx1 = Bv.x, cty1 = Bv.y, ctx2 = Bv.z, cty2 = Bv.w;
            const float cat  = Cv.z;
            const int   cls  = __float_as_int(Cv.w);

            #pragma unroll
            for (int rr = 0; rr < 4; rr++) {
                // intersection extents (FMNMX -> alu pipe, scalar)
                float m2x = fminf(Rx2[rr], ctx2);
                float M1x = fmaxf(Rx1[rr], ctx1);
                float m2y = fminf(Ry2[rr], cty2);
                float M1y = fmaxf(Ry1[rr], cty1);
                float wrx = fsub1(m2x, M1x);
                float wry = fsub1(m2y, M1y);
                float iw  = fmaxf(wrx, 0.f);
                float ih  = fmaxf(wry, 0.f);

                // enclosing extents: packed (w,h)+(wt,ht), then scalar subs
                float swx, swy;
                upk2(f2add(Rwh[rr], cwh), swx, swy);
                float exs = fsub1(swx, wrx);
                float eys = fsub1(swy, wry);

                float inter = iw * ih;
                float areae = exs * eys;
                float uni   = fsub1(fadd1(Ra[rr], cat), inter);
                // giou terms with single fast division
                float num = fmaf(inter, areae, uni * uni);
                float den = uni * areae;

                // packed 5*L1 diffs of normalized boxes
                float d1, d2, d3, d4;
                upk2(f2sub(Rn1[rr], cn1), d1, d2);
                upk2(f2sub(Rn2[rr], cn2), d3, d4);
                float s1 = fabsf(d1) + fabsf(d2);   // FADD with |.| operand mods
                float s2 = fabsf(d3) + fabsf(d4);
                float cb = fadd1(s1, s2);

                // pv = 2 - 2*p  (one LDG, all lanes on the same L1-resident row)
                float pv = __ldg(&prow[rr * NC_ + cls]);

                // C = cb + pv - 2*(num/den)
                float base = fadd1(cb, pv);
                res[rr][cc] = fnma2(__fdividef(num, den), base);
            }
        }

        // Coalesced float4 stores (warp covers 512B contiguous per rr)
        #pragma unroll
        for (int rr = 0; rr < 4; rr++) {
            size_t i = (size_t)(r0 + rloc + rr);
            float4 v = make_float4(res[rr][0], res[rr][1], res[rr][2], res[rr][3]);
            *reinterpret_cast<float4*>(out + i * BT_ + c0 + cloc) = v;
        }
    }
}

// ---------------------------------------------------------------------------
extern "C" void kernel_launch(void* const* d_in, const int* in_sizes, int n_in,
                              void* d_out, int out_size)
{
    const float* pred_logits  = (const float*)d_in[0];   // [B,Q,NC]
    const float* pred_boxes   = (const float*)d_in[1];   // [B,Q,4]
    const int*   tgt_labels   = (const int*)d_in[2];     // [B,T]
    const float* tgt_boxes    = (const float*)d_in[3];   // [B,T,4]
    const float* img_sz       = (const float*)d_in[4];   // [B,4]
    const float* img_sz_tgt   = (const float*)d_in[5];   // [B,T,4]
    float* out = (float*)d_out;

    prep_kernel<<<ROWBLKS + (BT_ + 255) / 256, 256>>>(
        pred_logits, pred_boxes, img_sz, tgt_boxes, tgt_labels, img_sz_tgt);

    dim3 grid(BT_ / TC, BQ_ / TR);   // (32, 250)
    cost_kernel<<<grid, 256>>>(out);
}

// round 16
// speedup vs baseline: 1.5644x; 1.5644x over previous
#include <cuda_runtime.h>
#include <cuda_bf16.h>
#include <cstdint>

// Problem constants
#define B_  32
#define Q_  500
#define T_  128
#define NC_ 80
#define BQ_ (B_ * Q_)     // 16000
#define BT_ (B_ * T_)     // 4096

#define TR 32             // tile rows
#define TC 128            // tile cols
#define SIDX(c) ((c) + ((c) >> 3))   // conflict-free float4 swizzle

// ---------------------------------------------------------------------------
// FFMA-imm helpers: rt_SMSP=1. Immediates perturbed 1 ulp so ptxas can't fold.
// ---------------------------------------------------------------------------
__device__ __forceinline__ float fadd1(float a, float c) {   // ~ a + c
    float d; asm("fma.rn.f32 %0, %1, 0f3F800001, %2;" : "=f"(d) : "f"(a), "f"(c)); return d;
}
__device__ __forceinline__ float fsub1(float a, float b) {   // ~ a - b
    float d; asm("fma.rn.f32 %0, %1, 0fBF800001, %2;" : "=f"(d) : "f"(b), "f"(a)); return d;
}
__device__ __forceinline__ float fnma2(float x, float c) {   // ~ c - 2*x
    float d; asm("fma.rn.f32 %0, %1, 0fC0000001, %2;" : "=f"(d) : "f"(x), "f"(c)); return d;
}

// ---------------------------------------------------------------------------
// Packed f32x2 helpers — ONLY add/sub (min/max.f32x2 do not exist in PTX).
// ---------------------------------------------------------------------------
__device__ __forceinline__ uint64_t pk2(float x, float y) {
    uint64_t r; asm("mov.b64 %0, {%1, %2};" : "=l"(r) : "f"(x), "f"(y)); return r;
}
__device__ __forceinline__ void upk2(uint64_t v, float& x, float& y) {
    asm("mov.b64 {%0, %1}, %2;" : "=f"(x), "=f"(y) : "l"(v));
}
__device__ __forceinline__ uint64_t f2add(uint64_t a, uint64_t b) {
    uint64_t d; asm("add.rn.f32x2 %0, %1, %2;" : "=l"(d) : "l"(a), "l"(b)); return d;
}
__device__ __forceinline__ uint64_t f2sub(uint64_t a, uint64_t b) {
    uint64_t d; asm("sub.rn.f32x2 %0, %1, %2;" : "=l"(d) : "l"(a), "l"(b)); return d;
}

// Scratch (device globals: allocation-free rule). SoA float4, TWO streams only.
__device__ float  g_prob[BQ_ * NC_];   // pv = 2 - 2*softmax, [row][cls]
__device__ float4 g_rowA[BQ_];         // 5*nx1, 5*ny1, 5*nx2, 5*ny2
__device__ float4 g_rowB[BQ_];         // x1, y1, x2, y2
__device__ float4 g_colA[BT_];         // 5*nx1 (cls in low 7 mantissa bits), 5*ny1, 5*nx2, 5*ny2
__device__ float4 g_colB[BT_];         // x1, y1, x2, y2

// ---------------------------------------------------------------------------
// Fused prep: blocks [0, BQ_/8) do softmax rows; blocks after do targets.
// ---------------------------------------------------------------------------
#define ROWBLKS (BQ_ / 8)   // 2000

__global__ void prep_kernel(const float* __restrict__ logits,
                            const float* __restrict__ boxes,
                            const float* __restrict__ img_sz,
                            const float* __restrict__ tboxes,
                            const int*   __restrict__ tlabels,
                            const float* __restrict__ img_sz_tgt)
{
    if (blockIdx.x < ROWBLKS) {
        // ---- per-query: softmax (stored as pv = 2-2p) + box precompute ----
        int row  = blockIdx.x * 8 + (threadIdx.x >> 5);
        int lane = threadIdx.x & 31;

        const float* lg = logits + (size_t)row * NC_;
        float v0 = lg[lane];
        float v1 = lg[lane + 32];
        float v2 = (lane < 16) ? lg[lane + 64] : -3.4e38f;

        float m = fmaxf(v0, fmaxf(v1, v2));
        #pragma unroll
        for (int o = 16; o; o >>= 1) m = fmaxf(m, __shfl_xor_sync(0xffffffffu, m, o));

        float e0 = __expf(v0 - m);
        float e1 = __expf(v1 - m);
        float e2 = (lane < 16) ? __expf(v2 - m) : 0.f;
        float s = e0 + e1 + e2;
        #pragma unroll
        for (int o = 16; o; o >>= 1) s += __shfl_xor_sync(0xffffffffu, s, o);

        float ninv2 = __fdividef(-2.f, s);
        float* pr = g_prob + (size_t)row * NC_;
        pr[lane]      = fmaf(e0, ninv2, 2.f);
        pr[lane + 32] = fmaf(e1, ninv2, 2.f);
        if (lane < 16) pr[lane + 64] = fmaf(e2, ninv2, 2.f);

        if (lane == 0) {
            int b = row / Q_;
            const float* bx = boxes + (size_t)row * 4;
            float x1 = bx[0], y1 = bx[1], x2 = bx[2], y2 = bx[3];
            float s0 = img_sz[b * 4 + 0], s1 = img_sz[b * 4 + 1];
            float s2 = img_sz[b * 4 + 2], s3 = img_sz[b * 4 + 3];
            g_rowA[row] = make_float4(__fdividef(5.f * x1, s0),
                                      __fdividef(5.f * y1, s1),
                                      __fdividef(5.f * x2, s2),
                                      __fdividef(5.f * y2, s3));
            g_rowB[row] = make_float4(x1, y1, x2, y2);
        }
    } else {
        // ---- per-target: box precompute + class id packed into nx1 LSBs ----
        int j = (blockIdx.x - ROWBLKS) * blockDim.x + threadIdx.x;
        if (j >= BT_) return;

        const float* bx = tboxes + (size_t)j * 4;
        const float* sz = img_sz_tgt + (size_t)j * 4;
        float x1 = bx[0], y1 = bx[1], x2 = bx[2], y2 = bx[3];
        float nx1 = __fdividef(5.f * x1, sz[0]);
        // steal low 7 mantissa bits for the class id (<=2^-17 rel perturbation)
        int cls = tlabels[j];
        int nb  = (__float_as_int(nx1) & ~0x7F) | (cls & 0x7F);
        g_colA[j] = make_float4(__int_as_float(nb),
                                __fdividef(5.f * y1, sz[1]),
                                __fdividef(5.f * x2, sz[2]),
                                __fdividef(5.f * y2, sz[3]));
        g_colB[j] = make_float4(x1, y1, x2, y2);
    }
}

// ---------------------------------------------------------------------------
// Main: cost matrix [BQ, BT]. Round-9 structure/math with the third SoA
// stream removed: w/h/area computed from xyxy (3 flops per col-group vs a
// 4-phase LDS.128), cls unpacked from nx1 mantissa LSBs. Col LDS phases
// per warp-tile: 48 -> 32.
// ---------------------------------------------------------------------------
__global__ __launch_bounds__(256, 3)
void cost_kernel(float* __restrict__ out)
{
    __shared__ float4 srA[TR], srB[TR];               // broadcast reads
    __shared__ float4 scA[TC + TC/8], scB[TC + TC/8];

    const int r0 = blockIdx.y * TR;
    const int c0 = blockIdx.x * TC;
    const int tid = threadIdx.x;

    if (tid < TC) {
        int si = SIDX(tid);
        scA[si] = g_colA[c0 + tid];
        scB[si] = g_colB[c0 + tid];
    } else if (tid < TC + TR) {
        int r = tid - TC;
        srA[r] = g_rowA[r0 + r];
        srB[r] = g_rowB[r0 + r];
    }
    __syncthreads();

    const int tc = tid & 31;       // column group (4 consecutive cols)
    const int tr = tid >> 5;       // warp -> row group
    const int rloc = tr * 4;
    const int cloc = tc * 4;

    // Row data into registers (broadcast LDS, N=1); w/h/area computed.
    float Rx1[4], Ry1[4], Rx2[4], Ry2[4];
    float Ra[4];
    uint64_t Rn1[4], Rn2[4], Rwh[4];
    #pragma unroll
    for (int rr = 0; rr < 4; rr++) {
        float4 A  = srA[rloc + rr];
        float4 Bv = srB[rloc + rr];
        Rn1[rr]  = pk2(A.x, A.y);
        Rn2[rr]  = pk2(A.z, A.w);
        Rx1[rr]  = Bv.x; Ry1[rr]  = Bv.y; Rx2[rr]  = Bv.z; Ry2[rr]  = Bv.w;
        float w  = Bv.z - Bv.x;
        float hh = Bv.w - Bv.y;
        Rwh[rr]  = pk2(w, hh);
        Ra[rr]   = w * hh;
    }

    const float* prow = g_prob + (size_t)(r0 + rloc) * NC_;

    float res[4][4];

    #pragma unroll
    for (int cc = 0; cc < 4; cc++) {
        const int si = SIDX(cloc + cc);
        const float4 A  = scA[si];   // 5*norm coords (cls in A.x LSBs)
        const float4 Bv = scB[si];   // xyxy
        const int   cls = __float_as_int(A.x) & 0x7F;
        const uint64_t cn1 = pk2(A.x, A.y);
        const uint64_t cn2 = pk2(A.z, A.w);
        const float ctx1 = Bv.x, cty1 = Bv.y, ctx2 = Bv.z, cty2 = Bv.w;
        const float cwt  = Bv.z - Bv.x;
        const float cht  = Bv.w - Bv.y;
        const float cat  = cwt * cht;
        const uint64_t cwh = pk2(cwt, cht);

        #pragma unroll
        for (int rr = 0; rr < 4; rr++) {
            // intersection extents (FMNMX -> alu pipe, scalar)
            float m2x = fminf(Rx2[rr], ctx2);
            float M1x = fmaxf(Rx1[rr], ctx1);
            float m2y = fminf(Ry2[rr], cty2);
            float M1y = fmaxf(Ry1[rr], cty1);
            float wrx = fsub1(m2x, M1x);
            float wry = fsub1(m2y, M1y);
            float iw  = fmaxf(wrx, 0.f);
            float ih  = fmaxf(wry, 0.f);

            // enclosing extents: packed (w,h)+(wt,ht), then scalar subs
            float swx, swy;
            upk2(f2add(Rwh[rr], cwh), swx, swy);
            float exs = fsub1(swx, wrx);
            float eys = fsub1(swy, wry);

            float inter = iw * ih;
            float areae = exs * eys;
            float uni   = fsub1(fadd1(Ra[rr], cat), inter);
            // giou terms with single fast division
            float num = fmaf(inter, areae, uni * uni);
            float den = uni * areae;

            // packed 5*L1 diffs of normalized boxes
            float d1, d2, d3, d4;
            upk2(f2sub(Rn1[rr], cn1), d1, d2);
            upk2(f2sub(Rn2[rr], cn2), d3, d4);
            float s1 = fabsf(d1) + fabsf(d2);   // FADD with |.| operand mods
            float s2 = fabsf(d3) + fabsf(d4);
            float cb = fadd1(s1, s2);

            // pv = 2 - 2*p  (one LDG, all lanes on the same L1-resident row)
            float pv = __ldg(&prow[rr * NC_ + cls]);

            // C = cb + pv - 2*(num/den)
            float base = fadd1(cb, pv);
            res[rr][cc] = fnma2(__fdividef(num, den), base);
        }
    }

    // Coalesced float4 stores (warp covers 512B contiguous per rr)
    #pragma unroll
    for (int rr = 0; rr < 4; rr++) {
        size_t i = (size_t)(r0 + rloc + rr);
        float4 v = make_float4(res[rr][0], res[rr][1], res[rr][2], res[rr][3]);
        *reinterpret_cast<float4*>(out + i * BT_ + c0 + cloc) = v;
    }
}

// ---------------------------------------------------------------------------
extern "C" void kernel_launch(void* const* d_in, const int* in_sizes, int n_in,
                              void* d_out, int out_size)
{
    const float* pred_logits  = (const float*)d_in[0];   // [B,Q,NC]
    const float* pred_boxes   = (const float*)d_in[1];   // [B,Q,4]
    const int*   tgt_labels   = (const int*)d_in[2];     // [B,T]
    const float* tgt_boxes    = (const float*)d_in[3];   // [B,T,4]
    const float* img_sz       = (const float*)d_in[4];   // [B,4]
    const float* img_sz_tgt   = (const float*)d_in[5];   // [B,T,4]
    float* out = (float*)d_out;

    prep_kernel<<<ROWBLKS + (BT_ + 255) / 256, 256>>>(
        pred_logits, pred_boxes, img_sz, tgt_boxes, tgt_labels, img_sz_tgt);

    dim3 grid(BT_ / TC, BQ_ / TR);   // (32, 500)
    cost_kernel<<<grid, 256>>>(out);
}